// round 8
// baseline (speedup 1.0000x reference)
#include <cuda_runtime.h>
#include <cuda_fp16.h>
#include <cstdint>

// Problem constants
#define B_   256
#define CIN  64
#define COUT 128
#define H_   1039
#define KN   6          // max neighbors
#define KT   7          // center + neighbors

// Static device scratch (allocation-guard safe)
__device__ __align__(256) __half g_x[(size_t)H_ * B_ * CIN];    // [h][b][c] fp16
__device__ __align__(256) __half g_wfrag[KT * COUT * CIN];      // fragment-order fp16
__device__ __align__(256) __half g_tmp[(size_t)H_ * COUT * B_]; // [h][o][b] fp16 (post scale+bias)

// ---------------------------------------------------------------------------
// PTX helpers (baseline ISA only — toolchain lowers through compute_103)
// ---------------------------------------------------------------------------
__device__ __forceinline__ uint32_t smem_u32(const void* p) {
    uint32_t r;
    asm("{ .reg .u64 t; cvta.to.shared.u64 t, %1; cvt.u32.u64 %0, t; }"
        : "=r"(r) : "l"(p));
    return r;
}
__device__ __forceinline__ void cpasync16(uint32_t s, const void* g) {
    asm volatile("cp.async.ca.shared.global [%0], [%1], 16;"
                 :: "r"(s), "l"(g) : "memory");
}
#define CP_COMMIT() asm volatile("cp.async.commit_group;" ::: "memory")
#define CP_WAIT(n)  asm volatile("cp.async.wait_group %0;" :: "n"(n) : "memory")

#define LDSM_X4(r, addr) \
    asm volatile("ldmatrix.sync.aligned.m8n8.x4.shared.b16 {%0,%1,%2,%3}, [%4];" \
                 : "=r"((r)[0]), "=r"((r)[1]), "=r"((r)[2]), "=r"((r)[3]) \
                 : "r"(addr))

__device__ __forceinline__ void mma_fp16(float* c, const uint32_t* a,
                                         uint32_t b0, uint32_t b1) {
    asm volatile(
        "mma.sync.aligned.m16n8k16.row.col.f32.f16.f16.f32 "
        "{%0,%1,%2,%3}, {%4,%5,%6,%7}, {%8,%9}, {%0,%1,%2,%3};"
        : "+f"(c[0]), "+f"(c[1]), "+f"(c[2]), "+f"(c[3])
        : "r"(a[0]), "r"(a[1]), "r"(a[2]), "r"(a[3]), "r"(b0), "r"(b1));
}

// ---------------------------------------------------------------------------
// Kernel 1: x[b][c][h] (viewed [m=bc][h]) -> g_x[h][m] fp16
// ---------------------------------------------------------------------------
__global__ void k_prep_x(const float* __restrict__ x) {
    __shared__ float t[32][33];
    const int h0 = blockIdx.x * 32;
    const int m0 = blockIdx.y * 32;
    const int tx = threadIdx.x, ty = threadIdx.y;

#pragma unroll
    for (int i = 0; i < 32; i += 8) {
        int h = h0 + tx;
        if (h < H_)
            t[ty + i][tx] = x[(size_t)(m0 + ty + i) * H_ + h];
    }
    __syncthreads();
#pragma unroll
    for (int i = 0; i < 32; i += 8) {
        int h = h0 + ty + i;
        int m = m0 + tx;
        if (h < H_)
            g_x[(size_t)h * (B_ * CIN) + m] = __float2half(t[tx][ty + i]);
    }
}

// ---------------------------------------------------------------------------
// Kernel 2: pack weights into per-lane MMA fragment order (fp16).
// addr16 = ((k*8 + MI)*4 + ks)*32 + lane; 8 halves per lane-chunk:
//   e = j*2 + hh (j = mma A reg 0..3)
//   row(o) = MI*16 + (j&1)*8 + (lane>>2)
//   col(c) = ks*16 + ((j>>1)&1)*8 + (lane&3)*2 + hh
// ---------------------------------------------------------------------------
__global__ void k_pack_w(const float* __restrict__ wc, const float* __restrict__ wn) {
    int t = blockIdx.x * blockDim.x + threadIdx.x;
    if (t >= KT * COUT * CIN) return;
    int k    = t >> 13;
    int rem  = t & 8191;
    int mi   = rem >> 10;
    int rem2 = rem & 1023;
    int ks   = rem2 >> 8;
    int rem3 = rem2 & 255;
    int ln   = rem3 >> 3;
    int e    = rem3 & 7;
    int j    = e >> 1;
    int hh   = e & 1;
    int o = mi * 16 + (j & 1) * 8 + (ln >> 2);
    int c = ks * 16 + ((j >> 1) & 1) * 8 + (ln & 3) * 2 + hh;
    float v = (k == 0) ? wc[o * CIN + c]
                       : wn[(o * CIN + c) * KN + (k - 1)];
    g_wfrag[t] = __float2half(v);
}

// ---------------------------------------------------------------------------
// Kernel 3: main HMMA GEMM, 2-hexagon persistent CTAs.
// Grid (2 b-halves, ceil(H/2)). CTA tile o=128 x b=128 per hexagon; each CTA
// runs hexagons h0=2*by and h0+1 back-to-back through one continuous 3-stage
// cp.async ring (prologue/drain amortized over both). 8 warps, warp tile
// 32(o) x 64(b), single fp16 term, fp32 accumulate, occupancy 2.
// A fragments LDG'd from L1-resident pre-packed weights. fp16 epilogue store.
// ---------------------------------------------------------------------------
#define BT_BYTES 16384                    // 128 rows x 128B
#define NSTAGE 3
#define DSMEM_BYTES (NSTAGE * BT_BYTES + 1024)
#define MAXCH (2 * KT)                    // max chunks across 2 hexagons

extern __shared__ char dsm[];

// swizzled smem offset for (row, 16B-chunk c) within a tile of 128B rows
__device__ __forceinline__ uint32_t swz(uint32_t row, uint32_t c) {
    return row * 128u + ((c ^ (row & 7u)) * 16u);
}

__global__ void __launch_bounds__(256, 2)
k_main(const int* __restrict__ neighbors, const float* __restrict__ bias) {
    __shared__ int   s_idx[MAXCH];   // gather h-index per chunk
    __shared__ int   s_wk[MAXCH];    // weight chunk index per chunk
    __shared__ int   s_n1, s_n;      // chunks for first hexagon / total
    __shared__ float s_scale[2];

    const int h0   = blockIdx.y * 2;
    const int bh   = blockIdx.x;          // b-half: rows bh*128 ..
    const int tid  = threadIdx.x;
    const int wid  = tid >> 5;
    const int lane = tid & 31;
    const int wo   = wid & 3;             // o 32-row group
    const int wb   = wid >> 2;            // b 64-half within the 128

    const uint32_t sraw  = smem_u32(dsm);
    const uint32_t sbase = (sraw + 1023u) & ~1023u;

    if (tid == 0) {
        int n = 0;
#pragma unroll
        for (int hh = 0; hh < 2; ++hh) {
            int h = h0 + hh;
            if (h < H_) {
                int start = n;
                s_idx[n] = h; s_wk[n] = 0; ++n;
#pragma unroll
                for (int k = 0; k < KN; ++k) {
                    int v = neighbors[h * KN + k];
                    if (v >= 0) { s_idx[n] = v; s_wk[n] = n - start; ++n; }
                }
                s_scale[hh] = 1.0f / (float)(n - start);
            }
            if (hh == 0) s_n1 = n;
        }
        s_n = n;
    }
    __syncthreads();

    const int n1 = s_n1;
    const int n  = s_n;
    const size_t boff = (size_t)bh * 128 * CIN;

    // ---- stage loader: chunk ci -> ring buffer j ----
    auto load_stage = [&](int ci, int j) {
        const char* Bsrc = (const char*)(g_x + (size_t)s_idx[ci] * (B_ * CIN) + boff);
        const uint32_t sb = sbase + (uint32_t)j * BT_BYTES;
#pragma unroll
        for (int p = 0; p < 4; ++p) {             // 1024 16B chunks
            int id = tid + p * 256;
            uint32_t sw = swz((uint32_t)(id >> 3), (uint32_t)(id & 7));
            cpasync16(sb + sw, Bsrc + (size_t)id * 16);
        }
    };

    float acc[2][8][4];
#pragma unroll
    for (int mi = 0; mi < 2; ++mi)
#pragma unroll
        for (int ni = 0; ni < 8; ++ni)
#pragma unroll
            for (int q = 0; q < 4; ++q) acc[mi][ni][q] = 0.0f;

    load_stage(0, 0); CP_COMMIT();
    load_stage(1, 1); CP_COMMIT();

    const uint32_t b_lr = (uint32_t)((lane & 7) + ((lane & 16) >> 1)); // 0..15
    const uint32_t b_lc = (uint32_t)((lane >> 3) & 1);

    const uint4* __restrict__ wf = (const uint4*)g_wfrag;

    // ---- epilogue: scale + bias, fp16 store to g_tmp[h][o][b] ----
    const int r     = lane >> 2;
    const int cpair = (lane & 3) * 2;
    auto epilogue = [&](int h, float sc) {
#pragma unroll
        for (int mi = 0; mi < 2; ++mi) {
            const int o0 = wo * 32 + mi * 16 + r;
            const float bi0 = bias[o0];
            const float bi8 = bias[o0 + 8];
            __half* d0 = g_tmp + ((size_t)h * COUT + o0) * B_ + bh * 128 + wb * 64 + cpair;
            __half* d8 = d0 + 8 * B_;
#pragma unroll
            for (int ni = 0; ni < 8; ++ni) {
                __half2 v0 = __floats2half2_rn(acc[mi][ni][0] * sc + bi0,
                                               acc[mi][ni][1] * sc + bi0);
                __half2 v8 = __floats2half2_rn(acc[mi][ni][2] * sc + bi8,
                                               acc[mi][ni][3] * sc + bi8);
                *(__half2*)(d0 + ni * 8) = v0;
                *(__half2*)(d8 + ni * 8) = v8;
                acc[mi][ni][0] = 0.0f; acc[mi][ni][1] = 0.0f;
                acc[mi][ni][2] = 0.0f; acc[mi][ni][3] = 0.0f;
            }
        }
    };

    for (int i = 0; i < n; ++i) {
        if (i < n - 1) { CP_WAIT(1); } else { CP_WAIT(0); }
        __syncthreads();

        if (i + 2 < n) { load_stage(i + 2, (i + 2) % NSTAGE); CP_COMMIT(); }

        const uint32_t st = sbase + (uint32_t)(i % NSTAGE) * BT_BYTES;
        const uint4* wfk = wf + (size_t)s_wk[i] * 1024;

#pragma unroll
        for (int ks = 0; ks < 4; ++ks) {
            uint32_t a[2][4];
#pragma unroll
            for (int mi = 0; mi < 2; ++mi) {
                int MI = wo * 2 + mi;                         // o-row group 0..7
                uint4 v = wfk[((MI * 4 + ks) * 32) + lane];
                a[mi][0] = v.x; a[mi][1] = v.y; a[mi][2] = v.z; a[mi][3] = v.w;
            }
            uint32_t b[4][4];
#pragma unroll
            for (int nt = 0; nt < 4; ++nt) {
                uint32_t row = (uint32_t)(wb * 64 + nt * 16) + b_lr;
                LDSM_X4(b[nt], st + swz(row, (uint32_t)(ks * 2) + b_lc));
            }
#pragma unroll
            for (int mi = 0; mi < 2; ++mi)
#pragma unroll
                for (int nt = 0; nt < 4; ++nt) {
                    mma_fp16(acc[mi][2 * nt],     a[mi], b[nt][0], b[nt][1]);
                    mma_fp16(acc[mi][2 * nt + 1], a[mi], b[nt][2], b[nt][3]);
                }
        }

        // hexagon-boundary epilogue (uniform branch; accumulators are
        // warp-local and valid right after mma.sync)
        if (i == n1 - 1) epilogue(h0, s_scale[0]);
    }
    if (n > n1) epilogue(h0 + 1, s_scale[1]);
}

// ---------------------------------------------------------------------------
// Kernel 4: tmp[h][o][b] (fp16) -> out[b][o][h] (fp32)  tiled transpose per o
// Tile 32(h) x 64(b); half2 vector reads (full 128B sectors), float2 staging.
// ---------------------------------------------------------------------------
__global__ void k_transpose_out(float* __restrict__ out) {
    __shared__ float2 t2[32][33];         // [h_local][b_pair]
    const int o  = blockIdx.z;
    const int h0 = blockIdx.x * 32;
    const int b0 = blockIdx.y * 64;
    const int tx = threadIdx.x, ty = threadIdx.y;

#pragma unroll
    for (int i = 0; i < 4; ++i) {
        int hl = ty + i * 8;
        int hh = h0 + hl;
        if (hh < H_) {
            __half2 v = *(const __half2*)(g_tmp + ((size_t)hh * COUT + o) * B_ + b0 + 2 * tx);
            t2[hl][tx] = __half22float2(v);
        }
    }
    __syncthreads();

    const int h = h0 + tx;
    if (h < H_) {
#pragma unroll
        for (int i = 0; i < 8; ++i) {
            int bl = ty + i * 8;               // 0..63
            float2 p = t2[tx][bl >> 1];
            float v = (bl & 1) ? p.y : p.x;
            out[((size_t)(b0 + bl) * COUT + o) * H_ + h] = v;
        }
    }
}

// ---------------------------------------------------------------------------
// Launch
// Inputs: x[f32], neighbors[int32], weight_center[f32], weight_neighbors[f32],
//         bias[f32]
// ---------------------------------------------------------------------------
extern "C" void kernel_launch(void* const* d_in, const int* in_sizes, int n_in,
                              void* d_out, int out_size) {
    const float* x    = (const float*)d_in[0];
    const int*   nb   = (const int*)d_in[1];
    const float* wc   = (const float*)d_in[2];
    const float* wn   = (const float*)d_in[3];
    const float* bias = (const float*)d_in[4];
    float* out = (float*)d_out;

    // 1) transpose + fp16 convert of x
    k_prep_x<<<dim3((H_ + 31) / 32, (B_ * CIN) / 32), dim3(32, 8)>>>(x);

    // 2) pack weights into fragment order
    k_pack_w<<<(KT * COUT * CIN + 255) / 256, 256>>>(wc, wn);

    // 3) main HMMA GEMM: 2 b-halves x ceil(H/2) persistent 2-hexagon CTAs
    cudaFuncSetAttribute(k_main, cudaFuncAttributeMaxDynamicSharedMemorySize,
                         DSMEM_BYTES);
    k_main<<<dim3(2, (H_ + 1) / 2), 256, DSMEM_BYTES>>>(nb, bias);

    // 4) transpose tmp -> out
    k_transpose_out<<<dim3((H_ + 31) / 32, B_ / 64, COUT), dim3(32, 8)>>>(out);
}

// round 9
// speedup vs baseline: 1.0683x; 1.0683x over previous
#include <cuda_runtime.h>
#include <cuda_fp16.h>
#include <cstdint>

// Problem constants
#define B_   256
#define CIN  64
#define COUT 128
#define H_   1039
#define KN   6          // max neighbors
#define KT   7          // center + neighbors

// Static device scratch (allocation-guard safe)
__device__ __align__(256) __half g_x[(size_t)H_ * B_ * CIN];    // [h][b][c] fp16
__device__ __align__(256) __half g_wfrag[KT * COUT * CIN];      // fragment-order fp16
__device__ __align__(256) __half g_tmp[(size_t)H_ * COUT * B_]; // [h][o][b] fp16 (post scale+bias)

// ---------------------------------------------------------------------------
// PTX helpers (baseline ISA only — toolchain lowers through compute_103)
// ---------------------------------------------------------------------------
__device__ __forceinline__ uint32_t smem_u32(const void* p) {
    uint32_t r;
    asm("{ .reg .u64 t; cvta.to.shared.u64 t, %1; cvt.u32.u64 %0, t; }"
        : "=r"(r) : "l"(p));
    return r;
}
__device__ __forceinline__ void cpasync16(uint32_t s, const void* g) {
    asm volatile("cp.async.ca.shared.global [%0], [%1], 16;"
                 :: "r"(s), "l"(g) : "memory");
}
#define CP_COMMIT() asm volatile("cp.async.commit_group;" ::: "memory")
#define CP_WAIT(n)  asm volatile("cp.async.wait_group %0;" :: "n"(n) : "memory")

#define LDSM_X4(r, addr) \
    asm volatile("ldmatrix.sync.aligned.m8n8.x4.shared.b16 {%0,%1,%2,%3}, [%4];" \
                 : "=r"((r)[0]), "=r"((r)[1]), "=r"((r)[2]), "=r"((r)[3]) \
                 : "r"(addr))

__device__ __forceinline__ void mma_fp16(float* c, const uint32_t* a,
                                         uint32_t b0, uint32_t b1) {
    asm volatile(
        "mma.sync.aligned.m16n8k16.row.col.f32.f16.f16.f32 "
        "{%0,%1,%2,%3}, {%4,%5,%6,%7}, {%8,%9}, {%0,%1,%2,%3};"
        : "+f"(c[0]), "+f"(c[1]), "+f"(c[2]), "+f"(c[3])
        : "r"(a[0]), "r"(a[1]), "r"(a[2]), "r"(a[3]), "r"(b0), "r"(b1));
}

// ---------------------------------------------------------------------------
// Kernel 1: x[b][c][h] (viewed [m=bc][h]) -> g_x[h][m] fp16
// ---------------------------------------------------------------------------
__global__ void k_prep_x(const float* __restrict__ x) {
    __shared__ float t[32][33];
    const int h0 = blockIdx.x * 32;
    const int m0 = blockIdx.y * 32;
    const int tx = threadIdx.x, ty = threadIdx.y;

#pragma unroll
    for (int i = 0; i < 32; i += 8) {
        int h = h0 + tx;
        if (h < H_)
            t[ty + i][tx] = x[(size_t)(m0 + ty + i) * H_ + h];
    }
    __syncthreads();
#pragma unroll
    for (int i = 0; i < 32; i += 8) {
        int h = h0 + ty + i;
        int m = m0 + tx;
        if (h < H_)
            g_x[(size_t)h * (B_ * CIN) + m] = __float2half(t[tx][ty + i]);
    }
}

// ---------------------------------------------------------------------------
// Kernel 2: pack weights into per-lane MMA fragment order (fp16).
// addr16 = ((k*8 + MI)*4 + ks)*32 + lane; 8 halves per lane-chunk:
//   e = j*2 + hh (j = mma A reg 0..3)
//   row(o) = MI*16 + (j&1)*8 + (lane>>2)
//   col(c) = ks*16 + ((j>>1)&1)*8 + (lane&3)*2 + hh
// ---------------------------------------------------------------------------
__global__ void k_pack_w(const float* __restrict__ wc, const float* __restrict__ wn) {
    int t = blockIdx.x * blockDim.x + threadIdx.x;
    if (t >= KT * COUT * CIN) return;
    int k    = t >> 13;
    int rem  = t & 8191;
    int mi   = rem >> 10;
    int rem2 = rem & 1023;
    int ks   = rem2 >> 8;
    int rem3 = rem2 & 255;
    int ln   = rem3 >> 3;
    int e    = rem3 & 7;
    int j    = e >> 1;
    int hh   = e & 1;
    int o = mi * 16 + (j & 1) * 8 + (ln >> 2);
    int c = ks * 16 + ((j >> 1) & 1) * 8 + (ln & 3) * 2 + hh;
    float v = (k == 0) ? wc[o * CIN + c]
                       : wn[(o * CIN + c) * KN + (k - 1)];
    g_wfrag[t] = __float2half(v);
}

// ---------------------------------------------------------------------------
// Kernel 3: main HMMA GEMM (R6 geometry + deeper pipeline).
// Grid (2 b-halves, H). CTA tile o=128 x b=128. 8 warps, warp tile 32(o) x
// 64(b). Single fp16 term, fp32 accumulate. 16KB B stages, 4-stage cp.async
// ring with distance-3 prefetch (CP_WAIT(2) steady state), one barrier per
// chunk, occupancy 2. A fragments LDG'd from L1-resident packed weights.
// fp16 epilogue store.
// ---------------------------------------------------------------------------
#define BT_BYTES 16384                    // 128 rows x 128B
#define NSTAGE 4
#define DSMEM_BYTES (NSTAGE * BT_BYTES + 1024)

extern __shared__ char dsm[];

// swizzled smem offset for (row, 16B-chunk c) within a tile of 128B rows
__device__ __forceinline__ uint32_t swz(uint32_t row, uint32_t c) {
    return row * 128u + ((c ^ (row & 7u)) * 16u);
}

__global__ void __launch_bounds__(256, 2)
k_main(const int* __restrict__ neighbors, const float* __restrict__ bias) {
    __shared__ int s_idx[KT];
    __shared__ int s_n;
    __shared__ float s_scale;

    const int h    = blockIdx.y;
    const int bh   = blockIdx.x;          // b-half: rows bh*128 .. bh*128+127
    const int tid  = threadIdx.x;
    const int wid  = tid >> 5;
    const int lane = tid & 31;
    const int wo   = wid & 3;             // o 32-row group
    const int wb   = wid >> 2;            // b 64-half within the 128

    const uint32_t sraw  = smem_u32(dsm);
    const uint32_t sbase = (sraw + 1023u) & ~1023u;

    if (tid == 0) {
        s_idx[0] = h;
        int n = 1;
#pragma unroll
        for (int k = 0; k < KN; ++k) {
            int v = neighbors[h * KN + k];
            if (v >= 0) s_idx[n++] = v;   // valid-prefix: slot i -> weight chunk i
        }
        s_n = n;
        s_scale = 1.0f / (float)n;
    }
    __syncthreads();

    const int n = s_n;                    // n in [4,7] (>=3 neighbors + center)
    const size_t boff = (size_t)bh * 128 * CIN;

    // ---- stage loader: chunk ci -> ring buffer j ----
    auto load_stage = [&](int ci, int j) {
        const char* Bsrc = (const char*)(g_x + (size_t)s_idx[ci] * (B_ * CIN) + boff);
        const uint32_t sb = sbase + (uint32_t)j * BT_BYTES;
#pragma unroll
        for (int p = 0; p < 4; ++p) {             // 1024 16B chunks
            int id = tid + p * 256;
            uint32_t sw = swz((uint32_t)(id >> 3), (uint32_t)(id & 7));
            cpasync16(sb + sw, Bsrc + (size_t)id * 16);
        }
    };

    float acc[2][8][4];
#pragma unroll
    for (int mi = 0; mi < 2; ++mi)
#pragma unroll
        for (int ni = 0; ni < 8; ++ni)
#pragma unroll
            for (int q = 0; q < 4; ++q) acc[mi][ni][q] = 0.0f;

    // prologue: 3 stages in flight (n >= 4 always)
    load_stage(0, 0); CP_COMMIT();
    load_stage(1, 1); CP_COMMIT();
    load_stage(2, 2); CP_COMMIT();

    const uint32_t b_lr = (uint32_t)((lane & 7) + ((lane & 16) >> 1)); // 0..15
    const uint32_t b_lc = (uint32_t)((lane >> 3) & 1);

    const uint4* __restrict__ wf = (const uint4*)g_wfrag;

    for (int i = 0; i < n; ++i) {
        // exact tail waits: committed = min(n, i+3); need stage i complete
        if (i <= n - 3)      { CP_WAIT(2); }
        else if (i == n - 2) { CP_WAIT(1); }
        else                 { CP_WAIT(0); }
        __syncthreads();            // stage i visible; all warps done with stage (i+1)%NSTAGE's previous tenant

        if (i + 3 < n) { load_stage(i + 3, (i + 3) % NSTAGE); CP_COMMIT(); }

        const uint32_t st = sbase + (uint32_t)(i % NSTAGE) * BT_BYTES;
        const uint4* wfk = wf + (size_t)i * 1024;

#pragma unroll
        for (int ks = 0; ks < 4; ++ks) {
            uint32_t a[2][4];
#pragma unroll
            for (int mi = 0; mi < 2; ++mi) {
                int MI = wo * 2 + mi;                         // o-row group 0..7
                uint4 v = wfk[((MI * 4 + ks) * 32) + lane];
                a[mi][0] = v.x; a[mi][1] = v.y; a[mi][2] = v.z; a[mi][3] = v.w;
            }
            uint32_t b[4][4];
#pragma unroll
            for (int nt = 0; nt < 4; ++nt) {
                uint32_t row = (uint32_t)(wb * 64 + nt * 16) + b_lr;
                LDSM_X4(b[nt], st + swz(row, (uint32_t)(ks * 2) + b_lc));
            }
#pragma unroll
            for (int mi = 0; mi < 2; ++mi)
#pragma unroll
                for (int nt = 0; nt < 4; ++nt) {
                    mma_fp16(acc[mi][2 * nt],     a[mi], b[nt][0], b[nt][1]);
                    mma_fp16(acc[mi][2 * nt + 1], a[mi], b[nt][2], b[nt][3]);
                }
        }
    }

    // ---- epilogue: scale + bias, fp16 store to g_tmp[h][o][b] ----
    const float sc = s_scale;
    const int r     = lane >> 2;
    const int cpair = (lane & 3) * 2;
#pragma unroll
    for (int mi = 0; mi < 2; ++mi) {
        const int o0 = wo * 32 + mi * 16 + r;
        const float bi0 = bias[o0];
        const float bi8 = bias[o0 + 8];
        __half* d0 = g_tmp + ((size_t)h * COUT + o0) * B_ + bh * 128 + wb * 64 + cpair;
        __half* d8 = d0 + 8 * B_;
#pragma unroll
        for (int ni = 0; ni < 8; ++ni) {
            __half2 v0 = __floats2half2_rn(acc[mi][ni][0] * sc + bi0,
                                           acc[mi][ni][1] * sc + bi0);
            __half2 v8 = __floats2half2_rn(acc[mi][ni][2] * sc + bi8,
                                           acc[mi][ni][3] * sc + bi8);
            *(__half2*)(d0 + ni * 8) = v0;
            *(__half2*)(d8 + ni * 8) = v8;
        }
    }
}

// ---------------------------------------------------------------------------
// Kernel 4: tmp[h][o][b] (fp16) -> out[b][o][h] (fp32)  tiled transpose per o
// Tile 32(h) x 64(b); half2 vector reads (full 128B sectors), float2 staging.
// ---------------------------------------------------------------------------
__global__ void k_transpose_out(float* __restrict__ out) {
    __shared__ float2 t2[32][33];         // [h_local][b_pair]
    const int o  = blockIdx.z;
    const int h0 = blockIdx.x * 32;
    const int b0 = blockIdx.y * 64;
    const int tx = threadIdx.x, ty = threadIdx.y;

#pragma unroll
    for (int i = 0; i < 4; ++i) {
        int hl = ty + i * 8;
        int hh = h0 + hl;
        if (hh < H_) {
            __half2 v = *(const __half2*)(g_tmp + ((size_t)hh * COUT + o) * B_ + b0 + 2 * tx);
            t2[hl][tx] = __half22float2(v);
        }
    }
    __syncthreads();

    const int h = h0 + tx;
    if (h < H_) {
#pragma unroll
        for (int i = 0; i < 8; ++i) {
            int bl = ty + i * 8;               // 0..63
            float2 p = t2[tx][bl >> 1];
            float v = (bl & 1) ? p.y : p.x;
            out[((size_t)(b0 + bl) * COUT + o) * H_ + h] = v;
        }
    }
}

// ---------------------------------------------------------------------------
// Launch
// Inputs: x[f32], neighbors[int32], weight_center[f32], weight_neighbors[f32],
//         bias[f32]
// ---------------------------------------------------------------------------
extern "C" void kernel_launch(void* const* d_in, const int* in_sizes, int n_in,
                              void* d_out, int out_size) {
    const float* x    = (const float*)d_in[0];
    const int*   nb   = (const int*)d_in[1];
    const float* wc   = (const float*)d_in[2];
    const float* wn   = (const float*)d_in[3];
    const float* bias = (const float*)d_in[4];
    float* out = (float*)d_out;

    // 1) transpose + fp16 convert of x
    k_prep_x<<<dim3((H_ + 31) / 32, (B_ * CIN) / 32), dim3(32, 8)>>>(x);

    // 2) pack weights into fragment order
    k_pack_w<<<(KT * COUT * CIN + 255) / 256, 256>>>(wc, wn);

    // 3) main HMMA GEMM, 2 CTAs per hexagon (b-halves)
    cudaFuncSetAttribute(k_main, cudaFuncAttributeMaxDynamicSharedMemorySize,
                         DSMEM_BYTES);
    k_main<<<dim3(2, H_), 256, DSMEM_BYTES>>>(nb, bias);

    // 4) transpose tmp -> out
    k_transpose_out<<<dim3((H_ + 31) / 32, B_ / 64, COUT), dim3(32, 8)>>>(out);
}

// round 10
// speedup vs baseline: 1.0880x; 1.0184x over previous
#include <cuda_runtime.h>
#include <cuda_fp16.h>
#include <cstdint>

// Problem constants
#define B_   256
#define CIN  64
#define COUT 128
#define H_   1039
#define KN   6          // max neighbors
#define KT   7          // center + neighbors

// Static device scratch (allocation-guard safe)
__device__ __align__(256) __half g_x[(size_t)H_ * B_ * CIN];    // [h][b][c] fp16
__device__ __align__(256) __half g_wfrag[KT * COUT * CIN];      // fragment-order fp16
__device__ __align__(256) __half g_tmp[(size_t)H_ * COUT * B_]; // [h][o][b] fp16 (post scale+bias)

// ---------------------------------------------------------------------------
// PTX helpers (baseline ISA only — toolchain lowers through compute_103)
// ---------------------------------------------------------------------------
__device__ __forceinline__ uint32_t smem_u32(const void* p) {
    uint32_t r;
    asm("{ .reg .u64 t; cvta.to.shared.u64 t, %1; cvt.u32.u64 %0, t; }"
        : "=r"(r) : "l"(p));
    return r;
}
__device__ __forceinline__ void cpasync16(uint32_t s, const void* g) {
    asm volatile("cp.async.ca.shared.global [%0], [%1], 16;"
                 :: "r"(s), "l"(g) : "memory");
}
#define CP_COMMIT() asm volatile("cp.async.commit_group;" ::: "memory")
#define CP_WAIT(n)  asm volatile("cp.async.wait_group %0;" :: "n"(n) : "memory")

#define LDSM_X4(r, addr) \
    asm volatile("ldmatrix.sync.aligned.m8n8.x4.shared.b16 {%0,%1,%2,%3}, [%4];" \
                 : "=r"((r)[0]), "=r"((r)[1]), "=r"((r)[2]), "=r"((r)[3]) \
                 : "r"(addr))

__device__ __forceinline__ void mma_fp16(float* c, const uint32_t* a,
                                         uint32_t b0, uint32_t b1) {
    asm volatile(
        "mma.sync.aligned.m16n8k16.row.col.f32.f16.f16.f32 "
        "{%0,%1,%2,%3}, {%4,%5,%6,%7}, {%8,%9}, {%0,%1,%2,%3};"
        : "+f"(c[0]), "+f"(c[1]), "+f"(c[2]), "+f"(c[3])
        : "r"(a[0]), "r"(a[1]), "r"(a[2]), "r"(a[3]), "r"(b0), "r"(b1));
}

// ---------------------------------------------------------------------------
// Kernel 1: x[b][c][h] (viewed [m=bc][h]) -> g_x[h][m] fp16
// ---------------------------------------------------------------------------
__global__ void k_prep_x(const float* __restrict__ x) {
    __shared__ float t[32][33];
    const int h0 = blockIdx.x * 32;
    const int m0 = blockIdx.y * 32;
    const int tx = threadIdx.x, ty = threadIdx.y;

#pragma unroll
    for (int i = 0; i < 32; i += 8) {
        int h = h0 + tx;
        if (h < H_)
            t[ty + i][tx] = x[(size_t)(m0 + ty + i) * H_ + h];
    }
    __syncthreads();
#pragma unroll
    for (int i = 0; i < 32; i += 8) {
        int h = h0 + ty + i;
        int m = m0 + tx;
        if (h < H_)
            g_x[(size_t)h * (B_ * CIN) + m] = __float2half(t[tx][ty + i]);
    }
}

// ---------------------------------------------------------------------------
// Kernel 2: pack weights into per-lane MMA fragment order (fp16).
// addr16 = ((k*8 + MI)*4 + ks)*32 + lane; 8 halves per lane-chunk:
//   e = j*2 + hh (j = mma A reg 0..3)
//   row(o) = MI*16 + (j&1)*8 + (lane>>2)
//   col(c) = ks*16 + ((j>>1)&1)*8 + (lane&3)*2 + hh
// ---------------------------------------------------------------------------
__global__ void k_pack_w(const float* __restrict__ wc, const float* __restrict__ wn) {
    int t = blockIdx.x * blockDim.x + threadIdx.x;
    if (t >= KT * COUT * CIN) return;
    int k    = t >> 13;
    int rem  = t & 8191;
    int mi   = rem >> 10;
    int rem2 = rem & 1023;
    int ks   = rem2 >> 8;
    int rem3 = rem2 & 255;
    int ln   = rem3 >> 3;
    int e    = rem3 & 7;
    int j    = e >> 1;
    int hh   = e & 1;
    int o = mi * 16 + (j & 1) * 8 + (ln >> 2);
    int c = ks * 16 + ((j >> 1) & 1) * 8 + (ln & 3) * 2 + hh;
    float v = (k == 0) ? wc[o * CIN + c]
                       : wn[(o * CIN + c) * KN + (k - 1)];
    g_wfrag[t] = __float2half(v);
}

// ---------------------------------------------------------------------------
// Kernel 3: main HMMA GEMM (R9 winner — at ~92% of legacy-HMMA ceiling).
// Grid (2 b-halves, H). CTA tile o=128 x b=128. 8 warps, warp tile 32(o) x
// 64(b). Single fp16 term, fp32 accumulate. 16KB B stages, 4-stage cp.async
// ring with distance-3 prefetch, one barrier per chunk, occupancy 2.
// ---------------------------------------------------------------------------
#define BT_BYTES 16384                    // 128 rows x 128B
#define NSTAGE 4
#define DSMEM_BYTES (NSTAGE * BT_BYTES + 1024)

extern __shared__ char dsm[];

// swizzled smem offset for (row, 16B-chunk c) within a tile of 128B rows
__device__ __forceinline__ uint32_t swz(uint32_t row, uint32_t c) {
    return row * 128u + ((c ^ (row & 7u)) * 16u);
}

__global__ void __launch_bounds__(256, 2)
k_main(const int* __restrict__ neighbors, const float* __restrict__ bias) {
    __shared__ int s_idx[KT];
    __shared__ int s_n;
    __shared__ float s_scale;

    const int h    = blockIdx.y;
    const int bh   = blockIdx.x;          // b-half: rows bh*128 .. bh*128+127
    const int tid  = threadIdx.x;
    const int wid  = tid >> 5;
    const int lane = tid & 31;
    const int wo   = wid & 3;             // o 32-row group
    const int wb   = wid >> 2;            // b 64-half within the 128

    const uint32_t sraw  = smem_u32(dsm);
    const uint32_t sbase = (sraw + 1023u) & ~1023u;

    if (tid == 0) {
        s_idx[0] = h;
        int n = 1;
#pragma unroll
        for (int k = 0; k < KN; ++k) {
            int v = neighbors[h * KN + k];
            if (v >= 0) s_idx[n++] = v;   // valid-prefix: slot i -> weight chunk i
        }
        s_n = n;
        s_scale = 1.0f / (float)n;
    }
    __syncthreads();

    const int n = s_n;                    // n in [4,7]
    const size_t boff = (size_t)bh * 128 * CIN;

    // ---- stage loader: chunk ci -> ring buffer j ----
    auto load_stage = [&](int ci, int j) {
        const char* Bsrc = (const char*)(g_x + (size_t)s_idx[ci] * (B_ * CIN) + boff);
        const uint32_t sb = sbase + (uint32_t)j * BT_BYTES;
#pragma unroll
        for (int p = 0; p < 4; ++p) {             // 1024 16B chunks
            int id = tid + p * 256;
            uint32_t sw = swz((uint32_t)(id >> 3), (uint32_t)(id & 7));
            cpasync16(sb + sw, Bsrc + (size_t)id * 16);
        }
    };

    float acc[2][8][4];
#pragma unroll
    for (int mi = 0; mi < 2; ++mi)
#pragma unroll
        for (int ni = 0; ni < 8; ++ni)
#pragma unroll
            for (int q = 0; q < 4; ++q) acc[mi][ni][q] = 0.0f;

    // prologue: 3 stages in flight (n >= 4 always)
    load_stage(0, 0); CP_COMMIT();
    load_stage(1, 1); CP_COMMIT();
    load_stage(2, 2); CP_COMMIT();

    const uint32_t b_lr = (uint32_t)((lane & 7) + ((lane & 16) >> 1)); // 0..15
    const uint32_t b_lc = (uint32_t)((lane >> 3) & 1);

    const uint4* __restrict__ wf = (const uint4*)g_wfrag;

    for (int i = 0; i < n; ++i) {
        if (i <= n - 3)      { CP_WAIT(2); }
        else if (i == n - 2) { CP_WAIT(1); }
        else                 { CP_WAIT(0); }
        __syncthreads();

        if (i + 3 < n) { load_stage(i + 3, (i + 3) % NSTAGE); CP_COMMIT(); }

        const uint32_t st = sbase + (uint32_t)(i % NSTAGE) * BT_BYTES;
        const uint4* wfk = wf + (size_t)i * 1024;

#pragma unroll
        for (int ks = 0; ks < 4; ++ks) {
            uint32_t a[2][4];
#pragma unroll
            for (int mi = 0; mi < 2; ++mi) {
                int MI = wo * 2 + mi;                         // o-row group 0..7
                uint4 v = wfk[((MI * 4 + ks) * 32) + lane];
                a[mi][0] = v.x; a[mi][1] = v.y; a[mi][2] = v.z; a[mi][3] = v.w;
            }
            uint32_t b[4][4];
#pragma unroll
            for (int nt = 0; nt < 4; ++nt) {
                uint32_t row = (uint32_t)(wb * 64 + nt * 16) + b_lr;
                LDSM_X4(b[nt], st + swz(row, (uint32_t)(ks * 2) + b_lc));
            }
#pragma unroll
            for (int mi = 0; mi < 2; ++mi)
#pragma unroll
                for (int nt = 0; nt < 4; ++nt) {
                    mma_fp16(acc[mi][2 * nt],     a[mi], b[nt][0], b[nt][1]);
                    mma_fp16(acc[mi][2 * nt + 1], a[mi], b[nt][2], b[nt][3]);
                }
        }
    }

    // ---- epilogue: scale + bias, fp16 store to g_tmp[h][o][b] ----
    const float sc = s_scale;
    const int r     = lane >> 2;
    const int cpair = (lane & 3) * 2;
#pragma unroll
    for (int mi = 0; mi < 2; ++mi) {
        const int o0 = wo * 32 + mi * 16 + r;
        const float bi0 = bias[o0];
        const float bi8 = bias[o0 + 8];
        __half* d0 = g_tmp + ((size_t)h * COUT + o0) * B_ + bh * 128 + wb * 64 + cpair;
        __half* d8 = d0 + 8 * B_;
#pragma unroll
        for (int ni = 0; ni < 8; ++ni) {
            __half2 v0 = __floats2half2_rn(acc[mi][ni][0] * sc + bi0,
                                           acc[mi][ni][1] * sc + bi0);
            __half2 v8 = __floats2half2_rn(acc[mi][ni][2] * sc + bi8,
                                           acc[mi][ni][3] * sc + bi8);
            *(__half2*)(d0 + ni * 8) = v0;
            *(__half2*)(d8 + ni * 8) = v8;
        }
    }
}

// ---------------------------------------------------------------------------
// Kernel 4: tmp[h][o][b] (fp16) -> out[b][o][h] (fp32)  tiled transpose per o
// Tile 64(h) x 64(b), 256 threads, 16 elems/thread. half2 vector reads
// (128B/warp), float2 smem staging, scalar coalesced writes (odd H_ forbids
// vector stores along h).
// ---------------------------------------------------------------------------
__global__ void __launch_bounds__(256)
k_transpose_out(float* __restrict__ out) {
    __shared__ float2 t2[64][33];         // [h_local][b_pair]
    const int o  = blockIdx.z;
    const int h0 = blockIdx.x * 64;
    const int b0 = blockIdx.y * 64;
    const int tid = threadIdx.x;

    // read: 8 passes, each warp covers one (h) row's 64 b as 32 half2
#pragma unroll
    for (int p = 0; p < 8; ++p) {
        int id  = tid + p * 256;
        int row = id >> 5;                 // 0..63
        int cp  = id & 31;                 // half2 index within 64 b
        int hh  = h0 + row;
        if (hh < H_) {
            __half2 v = *(const __half2*)(g_tmp + ((size_t)hh * COUT + o) * B_ + b0 + 2 * cp);
            t2[row][cp] = __half22float2(v);
        }
    }
    __syncthreads();

    // write: 16 passes; lanes map to consecutive h -> 128B coalesced stores
#pragma unroll
    for (int q = 0; q < 16; ++q) {
        int idx = tid + q * 256;
        int hl  = idx & 63;                // 0..63
        int bl  = idx >> 6;                // 0..63
        int h   = h0 + hl;
        if (h < H_) {
            float2 p2 = t2[hl][bl >> 1];
            float v = (bl & 1) ? p2.y : p2.x;
            out[((size_t)(b0 + bl) * COUT + o) * H_ + h] = v;
        }
    }
}

// ---------------------------------------------------------------------------
// Launch
// Inputs: x[f32], neighbors[int32], weight_center[f32], weight_neighbors[f32],
//         bias[f32]
// ---------------------------------------------------------------------------
extern "C" void kernel_launch(void* const* d_in, const int* in_sizes, int n_in,
                              void* d_out, int out_size) {
    const float* x    = (const float*)d_in[0];
    const int*   nb   = (const int*)d_in[1];
    const float* wc   = (const float*)d_in[2];
    const float* wn   = (const float*)d_in[3];
    const float* bias = (const float*)d_in[4];
    float* out = (float*)d_out;

    // 1) transpose + fp16 convert of x
    k_prep_x<<<dim3((H_ + 31) / 32, (B_ * CIN) / 32), dim3(32, 8)>>>(x);

    // 2) pack weights into fragment order
    k_pack_w<<<(KT * COUT * CIN + 255) / 256, 256>>>(wc, wn);

    // 3) main HMMA GEMM, 2 CTAs per hexagon (b-halves)
    cudaFuncSetAttribute(k_main, cudaFuncAttributeMaxDynamicSharedMemorySize,
                         DSMEM_BYTES);
    k_main<<<dim3(2, H_), 256, DSMEM_BYTES>>>(nb, bias);

    // 4) transpose tmp -> out (64x64 tiles)
    k_transpose_out<<<dim3((H_ + 63) / 64, B_ / 64, COUT), 256>>>(out);
}

// round 11
// speedup vs baseline: 1.0893x; 1.0013x over previous
#include <cuda_runtime.h>
#include <cuda_fp16.h>
#include <cstdint>

// Problem constants
#define B_   256
#define CIN  64
#define COUT 128
#define H_   1039
#define KN   6          // max neighbors
#define KT   7          // center + neighbors

// Static device scratch (allocation-guard safe)
__device__ __align__(256) __half g_x[(size_t)H_ * B_ * CIN];    // [h][b][c] fp16
__device__ __align__(256) __half g_wfrag[KT * COUT * CIN];      // fragment-order fp16
__device__ __align__(256) __half g_tmp[(size_t)H_ * COUT * B_]; // [h][o][b] fp16 (post scale+bias)

// ---------------------------------------------------------------------------
// PTX helpers (baseline ISA only — toolchain lowers through compute_103)
// ---------------------------------------------------------------------------
__device__ __forceinline__ uint32_t smem_u32(const void* p) {
    uint32_t r;
    asm("{ .reg .u64 t; cvta.to.shared.u64 t, %1; cvt.u32.u64 %0, t; }"
        : "=r"(r) : "l"(p));
    return r;
}
__device__ __forceinline__ void cpasync16(uint32_t s, const void* g) {
    asm volatile("cp.async.ca.shared.global [%0], [%1], 16;"
                 :: "r"(s), "l"(g) : "memory");
}
#define CP_COMMIT() asm volatile("cp.async.commit_group;" ::: "memory")
#define CP_WAIT(n)  asm volatile("cp.async.wait_group %0;" :: "n"(n) : "memory")

#define LDSM_X4(r, addr) \
    asm volatile("ldmatrix.sync.aligned.m8n8.x4.shared.b16 {%0,%1,%2,%3}, [%4];" \
                 : "=r"((r)[0]), "=r"((r)[1]), "=r"((r)[2]), "=r"((r)[3]) \
                 : "r"(addr))

__device__ __forceinline__ void mma_fp16(float* c, const uint32_t* a,
                                         uint32_t b0, uint32_t b1) {
    asm volatile(
        "mma.sync.aligned.m16n8k16.row.col.f32.f16.f16.f32 "
        "{%0,%1,%2,%3}, {%4,%5,%6,%7}, {%8,%9}, {%0,%1,%2,%3};"
        : "+f"(c[0]), "+f"(c[1]), "+f"(c[2]), "+f"(c[3])
        : "r"(a[0]), "r"(a[1]), "r"(a[2]), "r"(a[3]), "r"(b0), "r"(b1));
}

// ---------------------------------------------------------------------------
// Kernel 1: x[b][c][h] (viewed [m=bc][h]) -> g_x[h][m] fp16
// ---------------------------------------------------------------------------
__global__ void k_prep_x(const float* __restrict__ x) {
    __shared__ float t[32][33];
    const int h0 = blockIdx.x * 32;
    const int m0 = blockIdx.y * 32;
    const int tx = threadIdx.x, ty = threadIdx.y;

#pragma unroll
    for (int i = 0; i < 32; i += 8) {
        int h = h0 + tx;
        if (h < H_)
            t[ty + i][tx] = x[(size_t)(m0 + ty + i) * H_ + h];
    }
    __syncthreads();
#pragma unroll
    for (int i = 0; i < 32; i += 8) {
        int h = h0 + ty + i;
        int m = m0 + tx;
        if (h < H_)
            g_x[(size_t)h * (B_ * CIN) + m] = __float2half(t[tx][ty + i]);
    }
}

// ---------------------------------------------------------------------------
// Kernel 2: pack weights into per-lane MMA fragment order (fp16).
// addr16 = ((k*8 + MI)*4 + ks)*32 + lane; 8 halves per lane-chunk:
//   e = j*2 + hh (j = mma A reg 0..3)
//   row(o) = MI*16 + (j&1)*8 + (lane>>2)
//   col(c) = ks*16 + ((j>>1)&1)*8 + (lane&3)*2 + hh
// ---------------------------------------------------------------------------
__global__ void k_pack_w(const float* __restrict__ wc, const float* __restrict__ wn) {
    int t = blockIdx.x * blockDim.x + threadIdx.x;
    if (t >= KT * COUT * CIN) return;
    int k    = t >> 13;
    int rem  = t & 8191;
    int mi   = rem >> 10;
    int rem2 = rem & 1023;
    int ks   = rem2 >> 8;
    int rem3 = rem2 & 255;
    int ln   = rem3 >> 3;
    int e    = rem3 & 7;
    int j    = e >> 1;
    int hh   = e & 1;
    int o = mi * 16 + (j & 1) * 8 + (ln >> 2);
    int c = ks * 16 + ((j >> 1) & 1) * 8 + (ln & 3) * 2 + hh;
    float v = (k == 0) ? wc[o * CIN + c]
                       : wn[(o * CIN + c) * KN + (k - 1)];
    g_wfrag[t] = __float2half(v);
}

// ---------------------------------------------------------------------------
// Kernel 3: main HMMA GEMM (R9 winner — ~92% of legacy-HMMA ceiling).
// Grid (2 b-halves, H). CTA tile o=128 x b=128. 8 warps, warp tile 32(o) x
// 64(b). Single fp16 term, fp32 accumulate. 16KB B stages, 4-stage cp.async
// ring with distance-3 prefetch, one barrier per chunk, occupancy 2.
// ---------------------------------------------------------------------------
#define BT_BYTES 16384                    // 128 rows x 128B
#define NSTAGE 4
#define DSMEM_BYTES (NSTAGE * BT_BYTES + 1024)

extern __shared__ char dsm[];

// swizzled smem offset for (row, 16B-chunk c) within a tile of 128B rows
__device__ __forceinline__ uint32_t swz(uint32_t row, uint32_t c) {
    return row * 128u + ((c ^ (row & 7u)) * 16u);
}

__global__ void __launch_bounds__(256, 2)
k_main(const int* __restrict__ neighbors, const float* __restrict__ bias) {
    __shared__ int s_idx[KT];
    __shared__ int s_n;
    __shared__ float s_scale;

    const int h    = blockIdx.y;
    const int bh   = blockIdx.x;          // b-half: rows bh*128 .. bh*128+127
    const int tid  = threadIdx.x;
    const int wid  = tid >> 5;
    const int lane = tid & 31;
    const int wo   = wid & 3;             // o 32-row group
    const int wb   = wid >> 2;            // b 64-half within the 128

    const uint32_t sraw  = smem_u32(dsm);
    const uint32_t sbase = (sraw + 1023u) & ~1023u;

    if (tid == 0) {
        s_idx[0] = h;
        int n = 1;
#pragma unroll
        for (int k = 0; k < KN; ++k) {
            int v = neighbors[h * KN + k];
            if (v >= 0) s_idx[n++] = v;   // valid-prefix: slot i -> weight chunk i
        }
        s_n = n;
        s_scale = 1.0f / (float)n;
    }
    __syncthreads();

    const int n = s_n;                    // n in [4,7]
    const size_t boff = (size_t)bh * 128 * CIN;

    // ---- stage loader: chunk ci -> ring buffer j ----
    auto load_stage = [&](int ci, int j) {
        const char* Bsrc = (const char*)(g_x + (size_t)s_idx[ci] * (B_ * CIN) + boff);
        const uint32_t sb = sbase + (uint32_t)j * BT_BYTES;
#pragma unroll
        for (int p = 0; p < 4; ++p) {             // 1024 16B chunks
            int id = tid + p * 256;
            uint32_t sw = swz((uint32_t)(id >> 3), (uint32_t)(id & 7));
            cpasync16(sb + sw, Bsrc + (size_t)id * 16);
        }
    };

    float acc[2][8][4];
#pragma unroll
    for (int mi = 0; mi < 2; ++mi)
#pragma unroll
        for (int ni = 0; ni < 8; ++ni)
#pragma unroll
            for (int q = 0; q < 4; ++q) acc[mi][ni][q] = 0.0f;

    // prologue: 3 stages in flight (n >= 4 always)
    load_stage(0, 0); CP_COMMIT();
    load_stage(1, 1); CP_COMMIT();
    load_stage(2, 2); CP_COMMIT();

    const uint32_t b_lr = (uint32_t)((lane & 7) + ((lane & 16) >> 1)); // 0..15
    const uint32_t b_lc = (uint32_t)((lane >> 3) & 1);

    const uint4* __restrict__ wf = (const uint4*)g_wfrag;

    for (int i = 0; i < n; ++i) {
        if (i <= n - 3)      { CP_WAIT(2); }
        else if (i == n - 2) { CP_WAIT(1); }
        else                 { CP_WAIT(0); }
        __syncthreads();

        if (i + 3 < n) { load_stage(i + 3, (i + 3) % NSTAGE); CP_COMMIT(); }

        const uint32_t st = sbase + (uint32_t)(i % NSTAGE) * BT_BYTES;
        const uint4* wfk = wf + (size_t)i * 1024;

#pragma unroll
        for (int ks = 0; ks < 4; ++ks) {
            uint32_t a[2][4];
#pragma unroll
            for (int mi = 0; mi < 2; ++mi) {
                int MI = wo * 2 + mi;                         // o-row group 0..7
                uint4 v = wfk[((MI * 4 + ks) * 32) + lane];
                a[mi][0] = v.x; a[mi][1] = v.y; a[mi][2] = v.z; a[mi][3] = v.w;
            }
            uint32_t b[4][4];
#pragma unroll
            for (int nt = 0; nt < 4; ++nt) {
                uint32_t row = (uint32_t)(wb * 64 + nt * 16) + b_lr;
                LDSM_X4(b[nt], st + swz(row, (uint32_t)(ks * 2) + b_lc));
            }
#pragma unroll
            for (int mi = 0; mi < 2; ++mi)
#pragma unroll
                for (int nt = 0; nt < 4; ++nt) {
                    mma_fp16(acc[mi][2 * nt],     a[mi], b[nt][0], b[nt][1]);
                    mma_fp16(acc[mi][2 * nt + 1], a[mi], b[nt][2], b[nt][3]);
                }
        }
    }

    // ---- epilogue: scale + bias, fp16 store to g_tmp[h][o][b] ----
    const float sc = s_scale;
    const int r     = lane >> 2;
    const int cpair = (lane & 3) * 2;
#pragma unroll
    for (int mi = 0; mi < 2; ++mi) {
        const int o0 = wo * 32 + mi * 16 + r;
        const float bi0 = bias[o0];
        const float bi8 = bias[o0 + 8];
        __half* d0 = g_tmp + ((size_t)h * COUT + o0) * B_ + bh * 128 + wb * 64 + cpair;
        __half* d8 = d0 + 8 * B_;
#pragma unroll
        for (int ni = 0; ni < 8; ++ni) {
            __half2 v0 = __floats2half2_rn(acc[mi][ni][0] * sc + bi0,
                                           acc[mi][ni][1] * sc + bi0);
            __half2 v8 = __floats2half2_rn(acc[mi][ni][2] * sc + bi8,
                                           acc[mi][ni][3] * sc + bi8);
            *(__half2*)(d0 + ni * 8) = v0;
            *(__half2*)(d8 + ni * 8) = v8;
        }
    }
}

// ---------------------------------------------------------------------------
// Kernel 4: tmp[h][o][b] (fp16) -> out[b][o][h] (fp32)  tiled transpose per o
// Tile 64(h) x 64(b), 256 threads, 16 elems/thread. half2 staging (8.6 KB,
// conflict-free both sides), strength-reduced pointers: one base + constant
// stride per loop, uniform per-thread half-select on the write side.
// ---------------------------------------------------------------------------
__global__ void __launch_bounds__(256)
k_transpose_out(float* __restrict__ out) {
    __shared__ __half2 t2[64][33];        // [h_local][b_pair]
    const int o  = blockIdx.z;
    const int h0 = blockIdx.x * 64;
    const int b0 = blockIdx.y * 64;
    const int tid = threadIdx.x;

    // ---- read: 8 passes, fixed (row0, cp) per thread, constant stride ----
    {
        const int row0 = tid >> 5;         // 0..7
        const int cp   = tid & 31;         // half2 index within 64 b
        const __half* src = g_tmp + ((size_t)(h0 + row0) * COUT + o) * B_ + b0 + 2 * cp;
        const size_t sstep = (size_t)8 * COUT * B_;   // 8 h rows
#pragma unroll
        for (int p = 0; p < 8; ++p) {
            if (h0 + row0 + p * 8 < H_)
                t2[row0 + p * 8][cp] = *(const __half2*)(src + p * sstep);
        }
    }
    __syncthreads();

    // ---- write: 16 passes; hl pass-invariant, bl = bl0 + 4q ----
    {
        const int hl  = tid & 63;          // 0..63 (pass-invariant: 256 = 4*64)
        const int bl0 = tid >> 6;          // 0..3
        const int h   = h0 + hl;
        if (h < H_) {
            float* dst = out + ((size_t)(b0 + bl0) * COUT + o) * H_ + h;
            const size_t dstep = (size_t)4 * COUT * H_;   // 4 b rows
            const bool hi = (bl0 & 1);     // parity of bl is pass-invariant
#pragma unroll
            for (int q = 0; q < 16; ++q) {
                __half2 v = t2[hl][(bl0 + 4 * q) >> 1];
                dst[q * dstep] = hi ? __high2float(v) : __low2float(v);
            }
        }
    }
}

// ---------------------------------------------------------------------------
// Launch
// Inputs: x[f32], neighbors[int32], weight_center[f32], weight_neighbors[f32],
//         bias[f32]
// ---------------------------------------------------------------------------
extern "C" void kernel_launch(void* const* d_in, const int* in_sizes, int n_in,
                              void* d_out, int out_size) {
    const float* x    = (const float*)d_in[0];
    const int*   nb   = (const int*)d_in[1];
    const float* wc   = (const float*)d_in[2];
    const float* wn   = (const float*)d_in[3];
    const float* bias = (const float*)d_in[4];
    float* out = (float*)d_out;

    // 1) transpose + fp16 convert of x
    k_prep_x<<<dim3((H_ + 31) / 32, (B_ * CIN) / 32), dim3(32, 8)>>>(x);

    // 2) pack weights into fragment order
    k_pack_w<<<(KT * COUT * CIN + 255) / 256, 256>>>(wc, wn);

    // 3) main HMMA GEMM, 2 CTAs per hexagon (b-halves)
    cudaFuncSetAttribute(k_main, cudaFuncAttributeMaxDynamicSharedMemorySize,
                         DSMEM_BYTES);
    k_main<<<dim3(2, H_), 256, DSMEM_BYTES>>>(nb, bias);

    // 4) transpose tmp -> out (64x64 tiles)
    k_transpose_out<<<dim3((H_ + 63) / 64, B_ / 64, COUT), 256>>>(out);
}